// round 7
// baseline (speedup 1.0000x reference)
#include <cuda_runtime.h>
#include <cuda_fp16.h>
#include <mma.h>
#include <cstdint>

using namespace nvcuda;

#define BB 4
#define LL 2048
#define DD 1024
#define HH 16
#define DKH 64
#define GK 1024
#define GN 1024

// ---------------- bitcast helpers ----------------
__device__ __forceinline__ uint32_t h2u(__half2 h) {
    uint32_t u;
    *reinterpret_cast<__half2*>(&u) = h;
    return u;
}
__device__ __forceinline__ __half2 u2h(uint32_t u) {
    return *reinterpret_cast<__half2*>(&u);
}

// ---------------- scratch (static device allocations) ----------------
__device__ __half g_qx  [(size_t)BB * LL * DD];
__device__ __half g_kx  [(size_t)BB * LL * DD];
__device__ __half g_vx  [(size_t)BB * LL * DD];
__device__ __half g_sx  [(size_t)BB * LL * DD];
__device__ __half g_wq  [(size_t)DD * DD];
__device__ __half g_wk  [(size_t)DD * DD];
__device__ __half g_wv  [(size_t)DD * DD];
__device__ __half g_ws  [(size_t)DD * DD];
__device__ __half g_wo  [(size_t)DD * DD];
__device__ __half g_semo[(size_t)BB * LL * DD];
__device__ __half g_qp  [(size_t)BB * LL * DD];
__device__ __half g_kp  [(size_t)BB * LL * DD];
__device__ __half g_vp  [(size_t)BB * LL * DD];
__device__ __half g_op  [(size_t)BB * LL * DD];
__device__ __half g_ps  [(size_t)BB * HH * LL * LL];  // unnormalized P (half)
__device__ float  g_rinv[(size_t)BB * HH * LL];

// ================= fused f32 -> f16 conversions =================
__device__ __forceinline__ void cvt8(const float4* in, uint4* out, size_t i) {
    float4 a = in[i * 2], b = in[i * 2 + 1];
    uint4 o;
    o.x = h2u(__floats2half2_rn(a.x, a.y));
    o.y = h2u(__floats2half2_rn(a.z, a.w));
    o.z = h2u(__floats2half2_rn(b.x, b.y));
    o.w = h2u(__floats2half2_rn(b.z, b.w));
    out[i] = o;
}

__global__ __launch_bounds__(256) void cvt_inputs(
    const float4* q, const float4* k, const float4* v, const float4* s,
    uint4* oq, uint4* ok, uint4* ov, uint4* os)
{
    size_t i = (size_t)blockIdx.x * 256 + threadIdx.x;
    switch (blockIdx.y) {
        case 0: cvt8(q, oq, i); break;
        case 1: cvt8(k, ok, i); break;
        case 2: cvt8(v, ov, i); break;
        default: cvt8(s, os, i); break;
    }
}

__global__ __launch_bounds__(256) void cvt_weights(
    const float4* w0, const float4* w1, const float4* w2, const float4* w3, const float4* w4,
    uint4* o0, uint4* o1, uint4* o2, uint4* o3, uint4* o4)
{
    size_t i = (size_t)blockIdx.x * 256 + threadIdx.x;
    switch (blockIdx.y) {
        case 0: cvt8(w0, o0, i); break;
        case 1: cvt8(w1, o1, i); break;
        case 2: cvt8(w2, o2, i); break;
        case 3: cvt8(w3, o3, i); break;
        default: cvt8(w4, o4, i); break;
    }
}

// ================= fp16 GEMM, 128x128 tile (unchanged from R6) =================
#define HBM 128
#define HBN 128
#define HBK 32
#define HPAD 40
#define HNST 4
#define HNT (GK / HBK)
#define HSTG ((HBM + HBN) * HPAD)
#define HCPAD 132
#define HSMEM_BYTES (HNST * HSTG * 2)   // 81920

__device__ __forceinline__ void cpa16h(uint32_t saddr, const __half* src) {
    asm volatile("cp.async.cg.shared.global [%0], [%1], 16;\n" :: "r"(saddr), "l"(src));
}
__device__ __forceinline__ uint32_t smem_u32(const void* p) {
    uint32_t a;
    asm("{ .reg .u64 t; cvta.to.shared.u64 t, %1; cvt.u32.u64 %0, t; }" : "=r"(a) : "l"(p));
    return a;
}

template <typename OutT, bool HASADD>
__global__ __launch_bounds__(256, 2) void gemm_h(
    const __half* __restrict__ X, const __half* __restrict__ W,
    const float* __restrict__ bias, const __half* __restrict__ addend,
    OutT* __restrict__ C)
{
    extern __shared__ __half hsm[];
    const int tid = threadIdx.x;
    const int wid = tid >> 5;
    const int warp_m = wid & 3;
    const int warp_n = wid >> 2;
    const int m0 = blockIdx.y * HBM;
    const int n0 = blockIdx.x * HBN;
    const uint32_t smb = smem_u32(hsm);

    wmma::fragment<wmma::accumulator, 16, 16, 16, float> c[2][4];
    #pragma unroll
    for (int i = 0; i < 2; i++)
        #pragma unroll
        for (int j = 0; j < 4; j++) wmma::fill_fragment(c[i][j], 0.0f);

    auto stage = [&](int s, int k0) {
        uint32_t base = smb + (uint32_t)(s * HSTG) * 2;
        #pragma unroll
        for (int j = 0; j < 4; j++) {
            int idx = tid + 256 * j;
            if (idx < 512) {
                int r = idx >> 2, c8 = (idx & 3) * 8;
                cpa16h(base + (uint32_t)(r * HPAD + c8) * 2,
                       X + (size_t)(m0 + r) * GK + k0 + c8);
            } else {
                int i2 = idx - 512;
                int r = i2 >> 2, c8 = (i2 & 3) * 8;
                cpa16h(base + (uint32_t)((HBM + r) * HPAD + c8) * 2,
                       W + (size_t)(n0 + r) * GK + k0 + c8);
            }
        }
        asm volatile("cp.async.commit_group;\n");
    };

    #pragma unroll
    for (int s = 0; s < HNST - 1; s++) stage(s, s * HBK);

    for (int kt = 0; kt < HNT; kt++) {
        asm volatile("cp.async.wait_group %0;\n" :: "n"(HNST - 2));
        __syncthreads();

        const int ld = kt + HNST - 1;
        if (ld < HNT) stage(ld % HNST, ld * HBK);
        else asm volatile("cp.async.commit_group;\n");

        const __half* Xs = hsm + (kt % HNST) * HSTG;
        const __half* Ws = Xs + HBM * HPAD;
        #pragma unroll
        for (int kk = 0; kk < HBK; kk += 16) {
            wmma::fragment<wmma::matrix_a, 16, 16, 16, __half, wmma::row_major> a[2];
            #pragma unroll
            for (int i = 0; i < 2; i++)
                wmma::load_matrix_sync(a[i], Xs + (warp_m * 32 + i * 16) * HPAD + kk, HPAD);
            #pragma unroll
            for (int j = 0; j < 4; j++) {
                wmma::fragment<wmma::matrix_b, 16, 16, 16, __half, wmma::col_major> b;
                wmma::load_matrix_sync(b, Ws + (warp_n * 64 + j * 16) * HPAD + kk, HPAD);
                wmma::mma_sync(c[0][j], a[0], b, c[0][j]);
                wmma::mma_sync(c[1][j], a[1], b, c[1][j]);
            }
        }
    }

    asm volatile("cp.async.wait_group 0;\n");
    __syncthreads();

    float* Cs = (float*)hsm;
    #pragma unroll
    for (int i = 0; i < 2; i++)
        #pragma unroll
        for (int j = 0; j < 4; j++)
            wmma::store_matrix_sync(Cs + (warp_m * 32 + i * 16) * HCPAD + warp_n * 64 + j * 16,
                                    c[i][j], HCPAD, wmma::mem_row_major);
    __syncthreads();

    const int c4 = (tid & 31) * 4;
    const int r0 = tid >> 5;
    float4 bv = *(const float4*)(bias + n0 + c4);
    #pragma unroll
    for (int it = 0; it < 16; it++) {
        int rr = r0 + it * 8;
        size_t gi = (size_t)(m0 + rr) * GN + n0 + c4;
        float4 val = *(const float4*)(Cs + rr * HCPAD + c4);
        val.x += bv.x; val.y += bv.y; val.z += bv.z; val.w += bv.w;
        if (HASADD) {
            uint2 au = *(const uint2*)(addend + gi);
            __half2 a01 = u2h(au.x), a23 = u2h(au.y);
            val.x += __low2float(a01);  val.y += __high2float(a01);
            val.z += __low2float(a23);  val.w += __high2float(a23);
        }
        if (sizeof(OutT) == 2) {
            uint2 o;
            o.x = h2u(__floats2half2_rn(val.x, val.y));
            o.y = h2u(__floats2half2_rn(val.z, val.w));
            *(uint2*)((__half*)C + gi) = o;
        } else {
            *(float4*)((float*)C + gi) = val;
        }
    }
}

// ================= one-pass fp16 attention: 128 q-rows/block, cp.async KV double-buffer =================
#define AKP 72      // half row stride (K/V/P tiles)
#define SPADF 68    // float row stride (S tile)
#define EXPC 0.180336880111f   // log2(e) / 8
// dynamic smem layout in halves:
//   K   [2][64*AKP]  @ 0       (9216 halves)
//   V   [2][64*AKP]  @ 9216    (9216)
//   Ps  [128*AKP]    @ 18432   (9216)
//   Ss  (float)[128*SPADF] @ half-ofs 27648  (8704 floats = 17408 halves)
//   msh (__half2)[32]      @ half-ofs 45056  (64 halves)
#define AT_SMEM_BYTES ((45056 + 128) * 2)

__global__ __launch_bounds__(256) void attn_kernel(
    const __half* __restrict__ gq, const __half* __restrict__ gk, const __half* __restrict__ gv,
    const int* __restrict__ mask, __half* __restrict__ ps, __half* __restrict__ go,
    float* __restrict__ rinv_out)
{
    extern __shared__ __half asm_[];
    __half* Kbuf = asm_;
    __half* Vbuf = asm_ + 9216;
    __half* Ps   = asm_ + 18432;
    float*  Ss   = (float*)(asm_ + 27648);
    __half2* msh = (__half2*)(asm_ + 45056);
    const uint32_t smb = smem_u32(asm_);

    const int tid = threadIdx.x;
    const int wid = tid >> 5;          // 8 warps, each 16 q-rows x 64 cols
    const int b = blockIdx.z, h = blockIdx.y;
    const int q0 = blockIdx.x * 128;

    const __half* Qb = gq + ((size_t)(b * LL + q0)) * DD + h * DKH;
    const __half* Kb = gk + ((size_t)(b * LL)) * DD + h * DKH;
    const __half* Vb = gv + ((size_t)(b * LL)) * DD + h * DKH;

    // preload Q fragments: warp wid covers rows wid*16..wid*16+15, 4 k-steps of 16
    wmma::fragment<wmma::matrix_a, 16, 16, 16, __half, wmma::row_major> aq[4];
    #pragma unroll
    for (int ks = 0; ks < 4; ks++)
        wmma::load_matrix_sync(aq[ks], Qb + (size_t)(wid * 16) * DD + ks * 16, DD);

    const int r  = tid >> 1;            // q-row for elementwise (0..127)
    const int c0 = (tid & 1) * 32;      // 32-col half for elementwise
    const int mbase = b * LL;
    const size_t ps_base = ((size_t)(b * HH + h) * LL + q0) * LL;

    wmma::fragment<wmma::accumulator, 16, 16, 16, float> of[4];
    #pragma unroll
    for (int j = 0; j < 4; j++) wmma::fill_fragment(of[j], 0.0f);

    float racc = 0.0f;

    // stage K+V tile kt into buffer (kt&1): 1024 x 16B chunks, 4/thread
    auto stageKV = [&](int kt) {
        const int buf = kt & 1;
        const __half* Ksrc = Kb + (size_t)(kt * 64) * DD;
        const __half* Vsrc = Vb + (size_t)(kt * 64) * DD;
        const uint32_t kb = smb + (uint32_t)(buf * 64 * AKP) * 2;
        const uint32_t vb = smb + (uint32_t)((9216 + buf * 64 * AKP)) * 2;
        #pragma unroll
        for (int j = 0; j < 2; j++) {
            int idx = tid + 256 * j;
            int rr = idx >> 3, c8 = (idx & 7) * 8;
            cpa16h(kb + (uint32_t)(rr * AKP + c8) * 2, Ksrc + (size_t)rr * DD + c8);
            cpa16h(vb + (uint32_t)(rr * AKP + c8) * 2, Vsrc + (size_t)rr * DD + c8);
        }
        asm volatile("cp.async.commit_group;\n");
    };

    stageKV(0);

    for (int kt = 0; kt < 32; kt++) {
        const int buf = kt & 1;
        asm volatile("cp.async.wait_group 0;\n");
        if (tid < 32) {
            int m0v = mask[mbase + kt * 64 + tid * 2];
            int m1v = mask[mbase + kt * 64 + tid * 2 + 1];
            msh[tid] = __halves2half2(__int2half_rn(m0v), __int2half_rn(m1v));
        }
        __syncthreads();    // (a) KV[buf]+mask visible; all prev-iter PV reads done

        if (kt + 1 < 32) stageKV(kt + 1);   // prefetch overlaps compute below

        // S = Q K^T : warp -> 16 rows x 64 cols
        const __half* Kt = Kbuf + buf * 64 * AKP;
        wmma::fragment<wmma::accumulator, 16, 16, 16, float> cs[4];
        #pragma unroll
        for (int j = 0; j < 4; j++) wmma::fill_fragment(cs[j], 0.0f);
        #pragma unroll
        for (int ks = 0; ks < 4; ks++) {
            #pragma unroll
            for (int j = 0; j < 4; j++) {
                wmma::fragment<wmma::matrix_b, 16, 16, 16, __half, wmma::col_major> bk;
                wmma::load_matrix_sync(bk, Kt + (j * 16) * AKP + ks * 16, AKP);
                wmma::mma_sync(cs[j], aq[ks], bk, cs[j]);
            }
        }
        #pragma unroll
        for (int j = 0; j < 4; j++)
            wmma::store_matrix_sync(Ss + (wid * 16) * SPADF + j * 16, cs[j], SPADF, wmma::mem_row_major);
        __syncthreads();    // (b) S visible

        // p = mask * exp2(S * log2e/8); thread: row r, cols c0..c0+31
        const __half2* mrow = msh + (c0 >> 1);
        #pragma unroll
        for (int i4 = 0; i4 < 8; i4++) {
            int c = c0 + i4 * 4;
            float4 s4 = *(const float4*)(Ss + r * SPADF + c);
            uint32_t x01 = h2u(__floats2half2_rn(s4.x * EXPC, s4.y * EXPC));
            uint32_t x23 = h2u(__floats2half2_rn(s4.z * EXPC, s4.w * EXPC));
            uint32_t e01, e23;
            asm("ex2.approx.f16x2 %0, %1;" : "=r"(e01) : "r"(x01));
            asm("ex2.approx.f16x2 %0, %1;" : "=r"(e23) : "r"(x23));
            __half2 p01 = __hmul2(u2h(e01), mrow[i4 * 2]);
            __half2 p23 = __hmul2(u2h(e23), mrow[i4 * 2 + 1]);
            float2 f01 = __half22float2(p01);
            float2 f23 = __half22float2(p23);
            racc += f01.x + f01.y + f23.x + f23.y;
            uint2 hp;
            hp.x = h2u(p01);
            hp.y = h2u(p23);
            *(uint2*)(Ps + r * AKP + c) = hp;
            __stcs((uint2*)(ps + ps_base + (size_t)r * LL + kt * 64 + c), hp);
        }
        __syncthreads();    // (c) Ps visible

        // O += P V
        const __half* Vt = Vbuf + buf * 64 * AKP;
        #pragma unroll
        for (int ks = 0; ks < 4; ks++) {
            wmma::fragment<wmma::matrix_a, 16, 16, 16, __half, wmma::row_major> ap;
            wmma::load_matrix_sync(ap, Ps + (wid * 16) * AKP + ks * 16, AKP);
            #pragma unroll
            for (int j = 0; j < 4; j++) {
                wmma::fragment<wmma::matrix_b, 16, 16, 16, __half, wmma::row_major> bv;
                wmma::load_matrix_sync(bv, Vt + (ks * 16) * AKP + j * 16, AKP);
                wmma::mma_sync(of[j], ap, bv, of[j]);
            }
        }
        // no tail sync: next iter's (a) guards buffer reuse
    }

    // rowsum: pairs (tid, tid^1) share row r
    racc += __shfl_xor_sync(0xffffffff, racc, 1);
    const float rv = 1.0f / racc;
    if ((tid & 1) == 0) rinv_out[(size_t)(b * HH + h) * LL + q0 + r] = rv;

    // O epilogue
    __syncthreads();
    #pragma unroll
    for (int j = 0; j < 4; j++)
        wmma::store_matrix_sync(Ss + (wid * 16) * SPADF + j * 16, of[j], SPADF, wmma::mem_row_major);
    __syncthreads();
    {
        __half hrow[8];
        #pragma unroll
        for (int i4 = 0; i4 < 4; i4++) {
            int c = c0 + i4 * 8;
            float4 o0 = *(const float4*)(Ss + r * SPADF + c);
            float4 o1 = *(const float4*)(Ss + r * SPADF + c + 4);
            uint4 ho;
            ho.x = h2u(__floats2half2_rn(o0.x * rv, o0.y * rv));
            ho.y = h2u(__floats2half2_rn(o0.z * rv, o0.w * rv));
            ho.z = h2u(__floats2half2_rn(o1.x * rv, o1.y * rv));
            ho.w = h2u(__floats2half2_rn(o1.z * rv, o1.w * rv));
            *(uint4*)(go + (size_t)(b * LL + q0 + r) * DD + h * DKH + c) = ho;
        }
        (void)hrow;
    }
}

// ================= rescale: half P -> normalized f32 attn =================
__global__ __launch_bounds__(256) void rescale_kernel(
    const uint4* __restrict__ ps4, const float* __restrict__ rinv,
    float4* __restrict__ attn4)
{
    size_t f = (size_t)blockIdx.x * 256 + threadIdx.x;
    float s = __ldg(rinv + (f >> 8));
    uint4 u = __ldcs(ps4 + f);
    __half2 h0 = u2h(u.x), h1 = u2h(u.y);
    __half2 h2v = u2h(u.z), h3 = u2h(u.w);
    float4 o0, o1;
    o0.x = __low2float(h0) * s;  o0.y = __high2float(h0) * s;
    o0.z = __low2float(h1) * s;  o0.w = __high2float(h1) * s;
    o1.x = __low2float(h2v) * s; o1.y = __high2float(h2v) * s;
    o1.z = __low2float(h3) * s;  o1.w = __high2float(h3) * s;
    __stcs(attn4 + f * 2,     o0);
    __stcs(attn4 + f * 2 + 1, o1);
}

// ================= launch =================
extern "C" void kernel_launch(void* const* d_in, const int* in_sizes, int n_in,
                              void* d_out, int out_size)
{
    const float* q      = (const float*)d_in[0];
    const float* k      = (const float*)d_in[1];
    const float* v      = (const float*)d_in[2];
    const float* semf   = (const float*)d_in[3];
    const int*   mask   = (const int*)  d_in[4];
    const float* w_q    = (const float*)d_in[5];
    const float* b_q    = (const float*)d_in[6];
    const float* w_k    = (const float*)d_in[7];
    const float* b_k    = (const float*)d_in[8];
    const float* w_v    = (const float*)d_in[9];
    const float* b_v    = (const float*)d_in[10];
    const float* w_sem  = (const float*)d_in[11];
    const float* b_sem  = (const float*)d_in[12];
    const float* w_out  = (const float*)d_in[13];
    const float* b_out  = (const float*)d_in[14];

    float* out = (float*)d_out;
    const size_t attn_elems = (size_t)BB * HH * LL * LL;
    size_t attn_off = ((size_t)out_size >= attn_elems) ? (size_t)out_size - attn_elems : 0;
    float* attn = out + attn_off;

    __half *p_qx, *p_kx, *p_vx, *p_sx, *p_wq, *p_wk, *p_wv, *p_ws, *p_wo;
    __half *p_semo, *p_qp, *p_kp, *p_vp, *p_op, *p_ps;
    float *p_ri;
    cudaGetSymbolAddress((void**)&p_qx, g_qx);
    cudaGetSymbolAddress((void**)&p_kx, g_kx);
    cudaGetSymbolAddress((void**)&p_vx, g_vx);
    cudaGetSymbolAddress((void**)&p_sx, g_sx);
    cudaGetSymbolAddress((void**)&p_wq, g_wq);
    cudaGetSymbolAddress((void**)&p_wk, g_wk);
    cudaGetSymbolAddress((void**)&p_wv, g_wv);
    cudaGetSymbolAddress((void**)&p_ws, g_ws);
    cudaGetSymbolAddress((void**)&p_wo, g_wo);
    cudaGetSymbolAddress((void**)&p_semo, g_semo);
    cudaGetSymbolAddress((void**)&p_qp, g_qp);
    cudaGetSymbolAddress((void**)&p_kp, g_kp);
    cudaGetSymbolAddress((void**)&p_vp, g_vp);
    cudaGetSymbolAddress((void**)&p_op, g_op);
    cudaGetSymbolAddress((void**)&p_ps, g_ps);
    cudaGetSymbolAddress((void**)&p_ri, g_rinv);

    const size_t NBL = (size_t)BB * LL * DD;
    const size_t NW  = (size_t)DD * DD;

    cvt_inputs<<<dim3((unsigned)(NBL / 2048), 4), 256>>>(
        (const float4*)q, (const float4*)k, (const float4*)v, (const float4*)semf,
        (uint4*)p_qx, (uint4*)p_kx, (uint4*)p_vx, (uint4*)p_sx);
    cvt_weights<<<dim3((unsigned)(NW / 2048), 5), 256>>>(
        (const float4*)w_q, (const float4*)w_k, (const float4*)w_v,
        (const float4*)w_sem, (const float4*)w_out,
        (uint4*)p_wq, (uint4*)p_wk, (uint4*)p_wv, (uint4*)p_ws, (uint4*)p_wo);

    cudaFuncSetAttribute(gemm_h<__half, false>, cudaFuncAttributeMaxDynamicSharedMemorySize, HSMEM_BYTES);
    cudaFuncSetAttribute(gemm_h<__half, true >, cudaFuncAttributeMaxDynamicSharedMemorySize, HSMEM_BYTES);
    cudaFuncSetAttribute(gemm_h<float,  false>, cudaFuncAttributeMaxDynamicSharedMemorySize, HSMEM_BYTES);
    cudaFuncSetAttribute(attn_kernel, cudaFuncAttributeMaxDynamicSharedMemorySize, AT_SMEM_BYTES);

    dim3 gg(GN / HBN, (BB * LL) / HBM);   // (8, 64)

    gemm_h<__half, false><<<gg, 256, HSMEM_BYTES>>>(p_sx, p_ws, b_sem, nullptr, p_semo);
    gemm_h<__half, false><<<gg, 256, HSMEM_BYTES>>>(p_qx, p_wq, b_q,   nullptr, p_qp);
    gemm_h<__half, true ><<<gg, 256, HSMEM_BYTES>>>(p_kx, p_wk, b_k,   p_semo,  p_kp);
    gemm_h<__half, true ><<<gg, 256, HSMEM_BYTES>>>(p_vx, p_wv, b_v,   p_semo,  p_vp);

    attn_kernel<<<dim3(LL / 128, HH, BB), 256, AT_SMEM_BYTES>>>(
        p_qp, p_kp, p_vp, mask, p_ps, p_op, p_ri);

    rescale_kernel<<<(unsigned)(attn_elems / 2048), 256>>>((const uint4*)p_ps, p_ri, (float4*)attn);

    gemm_h<float, false><<<gg, 256, HSMEM_BYTES>>>(p_op, p_wo, b_out, nullptr, out);
}

// round 8
// speedup vs baseline: 1.0773x; 1.0773x over previous
#include <cuda_runtime.h>
#include <cuda_fp16.h>
#include <mma.h>
#include <cstdint>

using namespace nvcuda;

#define BB 4
#define LL 2048
#define DD 1024
#define HH 16
#define DKH 64
#define GK 1024
#define GN 1024

// ---------------- bitcast helpers ----------------
__device__ __forceinline__ uint32_t h2u(__half2 h) {
    uint32_t u;
    *reinterpret_cast<__half2*>(&u) = h;
    return u;
}
__device__ __forceinline__ __half2 u2h(uint32_t u) {
    return *reinterpret_cast<__half2*>(&u);
}

// ---------------- scratch (static device allocations) ----------------
__device__ __half g_qx  [(size_t)BB * LL * DD];
__device__ __half g_kx  [(size_t)BB * LL * DD];
__device__ __half g_vx  [(size_t)BB * LL * DD];
__device__ __half g_sx  [(size_t)BB * LL * DD];
__device__ __half g_wq  [(size_t)DD * DD];
__device__ __half g_wk  [(size_t)DD * DD];
__device__ __half g_wv  [(size_t)DD * DD];
__device__ __half g_ws  [(size_t)DD * DD];
__device__ __half g_wo  [(size_t)DD * DD];
__device__ __half g_semo[(size_t)BB * LL * DD];
__device__ __half g_qp  [(size_t)BB * LL * DD];
__device__ __half g_kp  [(size_t)BB * LL * DD];
__device__ __half g_vp  [(size_t)BB * LL * DD];
__device__ __half g_op  [(size_t)BB * LL * DD];
__device__ __half g_ps  [(size_t)BB * HH * LL * LL];  // unnormalized P (half)
__device__ float  g_rinv[(size_t)BB * HH * LL];

// ================= fused f32 -> f16 conversions =================
__device__ __forceinline__ void cvt8(const float4* in, uint4* out, size_t i) {
    float4 a = in[i * 2], b = in[i * 2 + 1];
    uint4 o;
    o.x = h2u(__floats2half2_rn(a.x, a.y));
    o.y = h2u(__floats2half2_rn(a.z, a.w));
    o.z = h2u(__floats2half2_rn(b.x, b.y));
    o.w = h2u(__floats2half2_rn(b.z, b.w));
    out[i] = o;
}

__global__ __launch_bounds__(256) void cvt_inputs(
    const float4* q, const float4* k, const float4* v, const float4* s,
    uint4* oq, uint4* ok, uint4* ov, uint4* os)
{
    size_t i = (size_t)blockIdx.x * 256 + threadIdx.x;
    switch (blockIdx.y) {
        case 0: cvt8(q, oq, i); break;
        case 1: cvt8(k, ok, i); break;
        case 2: cvt8(v, ov, i); break;
        default: cvt8(s, os, i); break;
    }
}

__global__ __launch_bounds__(256) void cvt_weights(
    const float4* w0, const float4* w1, const float4* w2, const float4* w3, const float4* w4,
    uint4* o0, uint4* o1, uint4* o2, uint4* o3, uint4* o4)
{
    size_t i = (size_t)blockIdx.x * 256 + threadIdx.x;
    switch (blockIdx.y) {
        case 0: cvt8(w0, o0, i); break;
        case 1: cvt8(w1, o1, i); break;
        case 2: cvt8(w2, o2, i); break;
        case 3: cvt8(w3, o3, i); break;
        default: cvt8(w4, o4, i); break;
    }
}

// ================= fp16 GEMM, 128x128 tile (unchanged from R6) =================
#define HBM 128
#define HBN 128
#define HBK 32
#define HPAD 40
#define HNST 4
#define HNT (GK / HBK)
#define HSTG ((HBM + HBN) * HPAD)
#define HCPAD 132
#define HSMEM_BYTES (HNST * HSTG * 2)   // 81920

__device__ __forceinline__ void cpa16h(uint32_t saddr, const __half* src) {
    asm volatile("cp.async.cg.shared.global [%0], [%1], 16;\n" :: "r"(saddr), "l"(src));
}
__device__ __forceinline__ uint32_t smem_u32(const void* p) {
    uint32_t a;
    asm("{ .reg .u64 t; cvta.to.shared.u64 t, %1; cvt.u32.u64 %0, t; }" : "=r"(a) : "l"(p));
    return a;
}

template <typename OutT, bool HASADD>
__global__ __launch_bounds__(256, 2) void gemm_h(
    const __half* __restrict__ X, const __half* __restrict__ W,
    const float* __restrict__ bias, const __half* __restrict__ addend,
    OutT* __restrict__ C)
{
    extern __shared__ __half hsm[];
    const int tid = threadIdx.x;
    const int wid = tid >> 5;
    const int warp_m = wid & 3;
    const int warp_n = wid >> 2;
    const int m0 = blockIdx.y * HBM;
    const int n0 = blockIdx.x * HBN;
    const uint32_t smb = smem_u32(hsm);

    wmma::fragment<wmma::accumulator, 16, 16, 16, float> c[2][4];
    #pragma unroll
    for (int i = 0; i < 2; i++)
        #pragma unroll
        for (int j = 0; j < 4; j++) wmma::fill_fragment(c[i][j], 0.0f);

    auto stage = [&](int s, int k0) {
        uint32_t base = smb + (uint32_t)(s * HSTG) * 2;
        #pragma unroll
        for (int j = 0; j < 4; j++) {
            int idx = tid + 256 * j;
            if (idx < 512) {
                int r = idx >> 2, c8 = (idx & 3) * 8;
                cpa16h(base + (uint32_t)(r * HPAD + c8) * 2,
                       X + (size_t)(m0 + r) * GK + k0 + c8);
            } else {
                int i2 = idx - 512;
                int r = i2 >> 2, c8 = (i2 & 3) * 8;
                cpa16h(base + (uint32_t)((HBM + r) * HPAD + c8) * 2,
                       W + (size_t)(n0 + r) * GK + k0 + c8);
            }
        }
        asm volatile("cp.async.commit_group;\n");
    };

    #pragma unroll
    for (int s = 0; s < HNST - 1; s++) stage(s, s * HBK);

    for (int kt = 0; kt < HNT; kt++) {
        asm volatile("cp.async.wait_group %0;\n" :: "n"(HNST - 2));
        __syncthreads();

        const int ld = kt + HNST - 1;
        if (ld < HNT) stage(ld % HNST, ld * HBK);
        else asm volatile("cp.async.commit_group;\n");

        const __half* Xs = hsm + (kt % HNST) * HSTG;
        const __half* Ws = Xs + HBM * HPAD;
        #pragma unroll
        for (int kk = 0; kk < HBK; kk += 16) {
            wmma::fragment<wmma::matrix_a, 16, 16, 16, __half, wmma::row_major> a[2];
            #pragma unroll
            for (int i = 0; i < 2; i++)
                wmma::load_matrix_sync(a[i], Xs + (warp_m * 32 + i * 16) * HPAD + kk, HPAD);
            #pragma unroll
            for (int j = 0; j < 4; j++) {
                wmma::fragment<wmma::matrix_b, 16, 16, 16, __half, wmma::col_major> b;
                wmma::load_matrix_sync(b, Ws + (warp_n * 64 + j * 16) * HPAD + kk, HPAD);
                wmma::mma_sync(c[0][j], a[0], b, c[0][j]);
                wmma::mma_sync(c[1][j], a[1], b, c[1][j]);
            }
        }
    }

    asm volatile("cp.async.wait_group 0;\n");
    __syncthreads();

    float* Cs = (float*)hsm;
    #pragma unroll
    for (int i = 0; i < 2; i++)
        #pragma unroll
        for (int j = 0; j < 4; j++)
            wmma::store_matrix_sync(Cs + (warp_m * 32 + i * 16) * HCPAD + warp_n * 64 + j * 16,
                                    c[i][j], HCPAD, wmma::mem_row_major);
    __syncthreads();

    const int c4 = (tid & 31) * 4;
    const int r0 = tid >> 5;
    float4 bv = *(const float4*)(bias + n0 + c4);
    #pragma unroll
    for (int it = 0; it < 16; it++) {
        int rr = r0 + it * 8;
        size_t gi = (size_t)(m0 + rr) * GN + n0 + c4;
        float4 val = *(const float4*)(Cs + rr * HCPAD + c4);
        val.x += bv.x; val.y += bv.y; val.z += bv.z; val.w += bv.w;
        if (HASADD) {
            uint2 au = *(const uint2*)(addend + gi);
            __half2 a01 = u2h(au.x), a23 = u2h(au.y);
            val.x += __low2float(a01);  val.y += __high2float(a01);
            val.z += __low2float(a23);  val.w += __high2float(a23);
        }
        if (sizeof(OutT) == 2) {
            uint2 o;
            o.x = h2u(__floats2half2_rn(val.x, val.y));
            o.y = h2u(__floats2half2_rn(val.z, val.w));
            *(uint2*)((__half*)C + gi) = o;
        } else {
            *(float4*)((float*)C + gi) = val;
        }
    }
}

// ================= one-pass fp16 attention: 64 q-rows, cp.async KV double-buffer =================
#define AKP 72      // half row stride (K/V/P tiles)
#define SPADF 68    // float row stride (S tile)
#define EXPC 0.180336880111f   // log2(e) / 8
// dynamic smem (halves):
//   K [2][64*AKP] @ 0      (9216)
//   V [2][64*AKP] @ 9216   (9216)
//   Ps  [64*AKP]  @ 18432  (4608)
//   Ss (float)[64*SPADF] @ 23040  (8704 halves)
//   msh (__half2)[32]    @ 31744  (64 halves)
#define ATO_V  9216
#define ATO_P  18432
#define ATO_S  23040
#define ATO_M  31744
#define AT_SMEM_BYTES ((ATO_M + 64 + 32) * 2)   // 63680 B -> 2 CTAs/SM

__global__ __launch_bounds__(256, 2) void attn_kernel(
    const __half* __restrict__ gq, const __half* __restrict__ gk, const __half* __restrict__ gv,
    const int* __restrict__ mask, __half* __restrict__ ps, __half* __restrict__ go,
    float* __restrict__ rinv_out)
{
    extern __shared__ __half asm_[];
    __half*  Kbuf = asm_;
    __half*  Vbuf = asm_ + ATO_V;
    __half*  Ps   = asm_ + ATO_P;
    float*   Ss   = (float*)(asm_ + ATO_S);
    __half2* msh  = (__half2*)(asm_ + ATO_M);
    const uint32_t smb = smem_u32(asm_);

    const int tid = threadIdx.x;
    const int wid = tid >> 5;
    const int warp_r = wid >> 1;       // 4 groups of 16 q-rows
    const int warp_c = wid & 1;        // 2 groups of 32 cols
    const int b = blockIdx.z, h = blockIdx.y;
    const int q0 = blockIdx.x * 64;

    const __half* Qb = gq + ((size_t)(b * LL + q0)) * DD + h * DKH;
    const __half* Kb = gk + ((size_t)(b * LL)) * DD + h * DKH;
    const __half* Vb = gv + ((size_t)(b * LL)) * DD + h * DKH;

    wmma::fragment<wmma::matrix_a, 16, 16, 16, __half, wmma::row_major> aq[4];
    #pragma unroll
    for (int ks = 0; ks < 4; ks++)
        wmma::load_matrix_sync(aq[ks], Qb + (size_t)(warp_r * 16) * DD + ks * 16, DD);

    const int r  = tid >> 2;
    const int c0 = (tid & 3) * 4;
    const int mbase = b * LL;
    const size_t ps_base = ((size_t)(b * HH + h) * LL + q0) * LL;

    wmma::fragment<wmma::accumulator, 16, 16, 16, float> of[2];
    wmma::fill_fragment(of[0], 0.0f);
    wmma::fill_fragment(of[1], 0.0f);

    float racc = 0.0f;

    // stage K+V tile kt into buffer (kt&1): 1024 x 16B chunks, 4/thread
    auto stageKV = [&](int kt) {
        const int buf = kt & 1;
        const __half* Ksrc = Kb + (size_t)(kt * 64) * DD;
        const __half* Vsrc = Vb + (size_t)(kt * 64) * DD;
        const uint32_t kb = smb + (uint32_t)(buf * 64 * AKP) * 2;
        const uint32_t vb = smb + (uint32_t)(ATO_V + buf * 64 * AKP) * 2;
        #pragma unroll
        for (int j = 0; j < 2; j++) {
            int idx = tid + 256 * j;
            int rr = idx >> 3, c8 = (idx & 7) * 8;
            cpa16h(kb + (uint32_t)(rr * AKP + c8) * 2, Ksrc + (size_t)rr * DD + c8);
            cpa16h(vb + (uint32_t)(rr * AKP + c8) * 2, Vsrc + (size_t)rr * DD + c8);
        }
        asm volatile("cp.async.commit_group;\n");
    };

    stageKV(0);

    for (int kt = 0; kt < 32; kt++) {
        const int buf = kt & 1;
        asm volatile("cp.async.wait_group 0;\n");
        if (tid < 32) {
            int m0v = mask[mbase + kt * 64 + tid * 2];
            int m1v = mask[mbase + kt * 64 + tid * 2 + 1];
            msh[tid] = __halves2half2(__int2half_rn(m0v), __int2half_rn(m1v));
        }
        __syncthreads();   // (a) KV[buf]+mask visible; prev PV reads done

        if (kt + 1 < 32) stageKV(kt + 1);   // prefetch into 1-buf, overlaps compute

        // S = Q K^T
        const __half* Kt = Kbuf + buf * 64 * AKP;
        wmma::fragment<wmma::accumulator, 16, 16, 16, float> cs[2];
        wmma::fill_fragment(cs[0], 0.0f);
        wmma::fill_fragment(cs[1], 0.0f);
        #pragma unroll
        for (int ks = 0; ks < 4; ks++) {
            wmma::fragment<wmma::matrix_b, 16, 16, 16, __half, wmma::col_major> bk[2];
            #pragma unroll
            for (int j = 0; j < 2; j++)
                wmma::load_matrix_sync(bk[j], Kt + (warp_c * 32 + j * 16) * AKP + ks * 16, AKP);
            wmma::mma_sync(cs[0], aq[ks], bk[0], cs[0]);
            wmma::mma_sync(cs[1], aq[ks], bk[1], cs[1]);
        }
        wmma::store_matrix_sync(Ss + (warp_r * 16) * SPADF + warp_c * 32,      cs[0], SPADF, wmma::mem_row_major);
        wmma::store_matrix_sync(Ss + (warp_r * 16) * SPADF + warp_c * 32 + 16, cs[1], SPADF, wmma::mem_row_major);
        __syncthreads();   // (b) S visible

        // p = mask * exp2(S * log2e/8)
        #pragma unroll
        for (int i4 = 0; i4 < 4; i4++) {
            int c = c0 + i4 * 16;
            float4 s4 = *(const float4*)(Ss + r * SPADF + c);
            uint32_t x01 = h2u(__floats2half2_rn(s4.x * EXPC, s4.y * EXPC));
            uint32_t x23 = h2u(__floats2half2_rn(s4.z * EXPC, s4.w * EXPC));
            uint32_t e01, e23;
            asm("ex2.approx.f16x2 %0, %1;" : "=r"(e01) : "r"(x01));
            asm("ex2.approx.f16x2 %0, %1;" : "=r"(e23) : "r"(x23));
            __half2 p01 = __hmul2(u2h(e01), msh[c >> 1]);
            __half2 p23 = __hmul2(u2h(e23), msh[(c >> 1) + 1]);
            float2 f01 = __half22float2(p01);
            float2 f23 = __half22float2(p23);
            racc += f01.x + f01.y + f23.x + f23.y;
            uint2 hp;
            hp.x = h2u(p01);
            hp.y = h2u(p23);
            *(uint2*)(Ps + r * AKP + c) = hp;
            __stcs((uint2*)(ps + ps_base + (size_t)r * LL + kt * 64 + c), hp);
        }
        __syncthreads();   // (c) Ps visible

        // O += P V
        const __half* Vt = Vbuf + buf * 64 * AKP;
        #pragma unroll
        for (int ks = 0; ks < 4; ks++) {
            wmma::fragment<wmma::matrix_a, 16, 16, 16, __half, wmma::row_major> ap;
            wmma::load_matrix_sync(ap, Ps + (warp_r * 16) * AKP + ks * 16, AKP);
            wmma::fragment<wmma::matrix_b, 16, 16, 16, __half, wmma::row_major> bv[2];
            #pragma unroll
            for (int j = 0; j < 2; j++)
                wmma::load_matrix_sync(bv[j], Vt + (ks * 16) * AKP + warp_c * 32 + j * 16, AKP);
            wmma::mma_sync(of[0], ap, bv[0], of[0]);
            wmma::mma_sync(of[1], ap, bv[1], of[1]);
        }
        // next iter's (a) sync guards Ps overwrite and V[buf] restage
    }

    racc += __shfl_xor_sync(0xffffffff, racc, 1);
    racc += __shfl_xor_sync(0xffffffff, racc, 2);
    const float rv = 1.0f / racc;
    if ((tid & 3) == 0) rinv_out[(size_t)(b * HH + h) * LL + q0 + r] = rv;

    // O epilogue
    __syncthreads();
    wmma::store_matrix_sync(Ss + (warp_r * 16) * SPADF + warp_c * 32,      of[0], SPADF, wmma::mem_row_major);
    wmma::store_matrix_sync(Ss + (warp_r * 16) * SPADF + warp_c * 32 + 16, of[1], SPADF, wmma::mem_row_major);
    __syncthreads();
    #pragma unroll
    for (int i4 = 0; i4 < 4; i4++) {
        int c = c0 + i4 * 16;
        float4 o4 = *(const float4*)(Ss + r * SPADF + c);
        uint2 ho;
        ho.x = h2u(__floats2half2_rn(o4.x * rv, o4.y * rv));
        ho.y = h2u(__floats2half2_rn(o4.z * rv, o4.w * rv));
        *(uint2*)(go + (size_t)(b * LL + q0 + r) * DD + h * DKH + c) = ho;
    }
}

// ================= rescale: half P -> normalized f32 attn =================
__global__ __launch_bounds__(256) void rescale_kernel(
    const uint4* __restrict__ ps4, const float* __restrict__ rinv,
    float4* __restrict__ attn4)
{
    size_t f = (size_t)blockIdx.x * 256 + threadIdx.x;
    float s = __ldg(rinv + (f >> 8));
    uint4 u = __ldcs(ps4 + f);
    __half2 h0 = u2h(u.x), h1 = u2h(u.y);
    __half2 h2v = u2h(u.z), h3 = u2h(u.w);
    float4 o0, o1;
    o0.x = __low2float(h0) * s;  o0.y = __high2float(h0) * s;
    o0.z = __low2float(h1) * s;  o0.w = __high2float(h1) * s;
    o1.x = __low2float(h2v) * s; o1.y = __high2float(h2v) * s;
    o1.z = __low2float(h3) * s;  o1.w = __high2float(h3) * s;
    __stcs(attn4 + f * 2,     o0);
    __stcs(attn4 + f * 2 + 1, o1);
}

// ================= launch =================
extern "C" void kernel_launch(void* const* d_in, const int* in_sizes, int n_in,
                              void* d_out, int out_size)
{
    const float* q      = (const float*)d_in[0];
    const float* k      = (const float*)d_in[1];
    const float* v      = (const float*)d_in[2];
    const float* semf   = (const float*)d_in[3];
    const int*   mask   = (const int*)  d_in[4];
    const float* w_q    = (const float*)d_in[5];
    const float* b_q    = (const float*)d_in[6];
    const float* w_k    = (const float*)d_in[7];
    const float* b_k    = (const float*)d_in[8];
    const float* w_v    = (const float*)d_in[9];
    const float* b_v    = (const float*)d_in[10];
    const float* w_sem  = (const float*)d_in[11];
    const float* b_sem  = (const float*)d_in[12];
    const float* w_out  = (const float*)d_in[13];
    const float* b_out  = (const float*)d_in[14];

    float* out = (float*)d_out;
    const size_t attn_elems = (size_t)BB * HH * LL * LL;
    size_t attn_off = ((size_t)out_size >= attn_elems) ? (size_t)out_size - attn_elems : 0;
    float* attn = out + attn_off;

    __half *p_qx, *p_kx, *p_vx, *p_sx, *p_wq, *p_wk, *p_wv, *p_ws, *p_wo;
    __half *p_semo, *p_qp, *p_kp, *p_vp, *p_op, *p_ps;
    float *p_ri;
    cudaGetSymbolAddress((void**)&p_qx, g_qx);
    cudaGetSymbolAddress((void**)&p_kx, g_kx);
    cudaGetSymbolAddress((void**)&p_vx, g_vx);
    cudaGetSymbolAddress((void**)&p_sx, g_sx);
    cudaGetSymbolAddress((void**)&p_wq, g_wq);
    cudaGetSymbolAddress((void**)&p_wk, g_wk);
    cudaGetSymbolAddress((void**)&p_wv, g_wv);
    cudaGetSymbolAddress((void**)&p_ws, g_ws);
    cudaGetSymbolAddress((void**)&p_wo, g_wo);
    cudaGetSymbolAddress((void**)&p_semo, g_semo);
    cudaGetSymbolAddress((void**)&p_qp, g_qp);
    cudaGetSymbolAddress((void**)&p_kp, g_kp);
    cudaGetSymbolAddress((void**)&p_vp, g_vp);
    cudaGetSymbolAddress((void**)&p_op, g_op);
    cudaGetSymbolAddress((void**)&p_ps, g_ps);
    cudaGetSymbolAddress((void**)&p_ri, g_rinv);

    const size_t NBL = (size_t)BB * LL * DD;
    const size_t NW  = (size_t)DD * DD;

    cvt_inputs<<<dim3((unsigned)(NBL / 2048), 4), 256>>>(
        (const float4*)q, (const float4*)k, (const float4*)v, (const float4*)semf,
        (uint4*)p_qx, (uint4*)p_kx, (uint4*)p_vx, (uint4*)p_sx);
    cvt_weights<<<dim3((unsigned)(NW / 2048), 5), 256>>>(
        (const float4*)w_q, (const float4*)w_k, (const float4*)w_v,
        (const float4*)w_sem, (const float4*)w_out,
        (uint4*)p_wq, (uint4*)p_wk, (uint4*)p_wv, (uint4*)p_ws, (uint4*)p_wo);

    cudaFuncSetAttribute(gemm_h<__half, false>, cudaFuncAttributeMaxDynamicSharedMemorySize, HSMEM_BYTES);
    cudaFuncSetAttribute(gemm_h<__half, true >, cudaFuncAttributeMaxDynamicSharedMemorySize, HSMEM_BYTES);
    cudaFuncSetAttribute(gemm_h<float,  false>, cudaFuncAttributeMaxDynamicSharedMemorySize, HSMEM_BYTES);
    cudaFuncSetAttribute(attn_kernel, cudaFuncAttributeMaxDynamicSharedMemorySize, AT_SMEM_BYTES);

    dim3 gg(GN / HBN, (BB * LL) / HBM);   // (8, 64)

    gemm_h<__half, false><<<gg, 256, HSMEM_BYTES>>>(p_sx, p_ws, b_sem, nullptr, p_semo);
    gemm_h<__half, false><<<gg, 256, HSMEM_BYTES>>>(p_qx, p_wq, b_q,   nullptr, p_qp);
    gemm_h<__half, true ><<<gg, 256, HSMEM_BYTES>>>(p_kx, p_wk, b_k,   p_semo,  p_kp);
    gemm_h<__half, true ><<<gg, 256, HSMEM_BYTES>>>(p_vx, p_wv, b_v,   p_semo,  p_vp);

    attn_kernel<<<dim3(LL / 64, HH, BB), 256, AT_SMEM_BYTES>>>(
        p_qp, p_kp, p_vp, mask, p_ps, p_op, p_ri);

    rescale_kernel<<<(unsigned)(attn_elems / 2048), 256>>>((const uint4*)p_ps, p_ri, (float4*)attn);

    gemm_h<float, false><<<gg, 256, HSMEM_BYTES>>>(p_op, p_wo, b_out, nullptr, out);
}

// round 9
// speedup vs baseline: 1.2515x; 1.1617x over previous
#include <cuda_runtime.h>
#include <cuda_fp16.h>
#include <mma.h>
#include <cstdint>

using namespace nvcuda;

#define BB 4
#define LL 2048
#define DD 1024
#define HH 16
#define DKH 64
#define GK 1024
#define GN 1024

// ---------------- bitcast helpers ----------------
__device__ __forceinline__ uint32_t h2u(__half2 h) {
    uint32_t u;
    *reinterpret_cast<__half2*>(&u) = h;
    return u;
}
__device__ __forceinline__ __half2 u2h(uint32_t u) {
    return *reinterpret_cast<__half2*>(&u);
}

// ---------------- scratch (static device allocations) ----------------
__device__ __half g_qx  [(size_t)BB * LL * DD];
__device__ __half g_kx  [(size_t)BB * LL * DD];
__device__ __half g_vx  [(size_t)BB * LL * DD];
__device__ __half g_sx  [(size_t)BB * LL * DD];
__device__ __half g_wq  [(size_t)DD * DD];
__device__ __half g_wk  [(size_t)DD * DD];
__device__ __half g_wv  [(size_t)DD * DD];
__device__ __half g_ws  [(size_t)DD * DD];
__device__ __half g_wo  [(size_t)DD * DD];
__device__ __half g_semo[(size_t)BB * LL * DD];
__device__ __half g_qp  [(size_t)BB * LL * DD];
__device__ __half g_kp  [(size_t)BB * LL * DD];
__device__ __half g_vp  [(size_t)BB * LL * DD];
__device__ __half g_op  [(size_t)BB * LL * DD];
__device__ __half g_ps  [(size_t)BB * HH * LL * LL];  // unnormalized P (half)
__device__ float  g_rinv[(size_t)BB * HH * LL];

// ================= fused f32 -> f16 conversions =================
__device__ __forceinline__ void cvt8(const float4* in, uint4* out, size_t i) {
    float4 a = in[i * 2], b = in[i * 2 + 1];
    uint4 o;
    o.x = h2u(__floats2half2_rn(a.x, a.y));
    o.y = h2u(__floats2half2_rn(a.z, a.w));
    o.z = h2u(__floats2half2_rn(b.x, b.y));
    o.w = h2u(__floats2half2_rn(b.z, b.w));
    out[i] = o;
}

__global__ __launch_bounds__(256) void cvt_inputs(
    const float4* q, const float4* k, const float4* v, const float4* s,
    uint4* oq, uint4* ok, uint4* ov, uint4* os)
{
    size_t i = (size_t)blockIdx.x * 256 + threadIdx.x;
    switch (blockIdx.y) {
        case 0: cvt8(q, oq, i); break;
        case 1: cvt8(k, ok, i); break;
        case 2: cvt8(v, ov, i); break;
        default: cvt8(s, os, i); break;
    }
}

__global__ __launch_bounds__(256) void cvt_weights(
    const float4* w0, const float4* w1, const float4* w2, const float4* w3, const float4* w4,
    uint4* o0, uint4* o1, uint4* o2, uint4* o3, uint4* o4)
{
    size_t i = (size_t)blockIdx.x * 256 + threadIdx.x;
    switch (blockIdx.y) {
        case 0: cvt8(w0, o0, i); break;
        case 1: cvt8(w1, o1, i); break;
        case 2: cvt8(w2, o2, i); break;
        case 3: cvt8(w3, o3, i); break;
        default: cvt8(w4, o4, i); break;
    }
}

// ================= fp16 GEMM, 128x128 tile (R6 core) =================
#define HBM 128
#define HBN 128
#define HBK 32
#define HPAD 40
#define HNST 4
#define HNT (GK / HBK)
#define HSTG ((HBM + HBN) * HPAD)
#define HCPAD 132
#define HSMEM_BYTES (HNST * HSTG * 2)   // 81920

__device__ __forceinline__ void cpa16h(uint32_t saddr, const __half* src) {
    asm volatile("cp.async.cg.shared.global [%0], [%1], 16;\n" :: "r"(saddr), "l"(src));
}
__device__ __forceinline__ uint32_t smem_u32(const void* p) {
    uint32_t a;
    asm("{ .reg .u64 t; cvta.to.shared.u64 t, %1; cvt.u32.u64 %0, t; }" : "=r"(a) : "l"(p));
    return a;
}

template <typename OutT>
__device__ __forceinline__ void gemm_core(
    const __half* __restrict__ X, const __half* __restrict__ W,
    const float* __restrict__ bias, const __half* __restrict__ addend,
    OutT* __restrict__ C, __half* hsm, int m0, int n0)
{
    const int tid = threadIdx.x;
    const int wid = tid >> 5;
    const int warp_m = wid & 3;
    const int warp_n = wid >> 2;
    const uint32_t smb = smem_u32(hsm);

    wmma::fragment<wmma::accumulator, 16, 16, 16, float> c[2][4];
    #pragma unroll
    for (int i = 0; i < 2; i++)
        #pragma unroll
        for (int j = 0; j < 4; j++) wmma::fill_fragment(c[i][j], 0.0f);

    auto stage = [&](int s, int k0) {
        uint32_t base = smb + (uint32_t)(s * HSTG) * 2;
        #pragma unroll
        for (int j = 0; j < 4; j++) {
            int idx = tid + 256 * j;
            if (idx < 512) {
                int r = idx >> 2, c8 = (idx & 3) * 8;
                cpa16h(base + (uint32_t)(r * HPAD + c8) * 2,
                       X + (size_t)(m0 + r) * GK + k0 + c8);
            } else {
                int i2 = idx - 512;
                int r = i2 >> 2, c8 = (i2 & 3) * 8;
                cpa16h(base + (uint32_t)((HBM + r) * HPAD + c8) * 2,
                       W + (size_t)(n0 + r) * GK + k0 + c8);
            }
        }
        asm volatile("cp.async.commit_group;\n");
    };

    #pragma unroll
    for (int s = 0; s < HNST - 1; s++) stage(s, s * HBK);

    for (int kt = 0; kt < HNT; kt++) {
        asm volatile("cp.async.wait_group %0;\n" :: "n"(HNST - 2));
        __syncthreads();

        const int ld = kt + HNST - 1;
        if (ld < HNT) stage(ld % HNST, ld * HBK);
        else asm volatile("cp.async.commit_group;\n");

        const __half* Xs = hsm + (kt % HNST) * HSTG;
        const __half* Ws = Xs + HBM * HPAD;
        #pragma unroll
        for (int kk = 0; kk < HBK; kk += 16) {
            wmma::fragment<wmma::matrix_a, 16, 16, 16, __half, wmma::row_major> a[2];
            #pragma unroll
            for (int i = 0; i < 2; i++)
                wmma::load_matrix_sync(a[i], Xs + (warp_m * 32 + i * 16) * HPAD + kk, HPAD);
            #pragma unroll
            for (int j = 0; j < 4; j++) {
                wmma::fragment<wmma::matrix_b, 16, 16, 16, __half, wmma::col_major> b;
                wmma::load_matrix_sync(b, Ws + (warp_n * 64 + j * 16) * HPAD + kk, HPAD);
                wmma::mma_sync(c[0][j], a[0], b, c[0][j]);
                wmma::mma_sync(c[1][j], a[1], b, c[1][j]);
            }
        }
    }

    asm volatile("cp.async.wait_group 0;\n");
    __syncthreads();

    float* Cs = (float*)hsm;
    #pragma unroll
    for (int i = 0; i < 2; i++)
        #pragma unroll
        for (int j = 0; j < 4; j++)
            wmma::store_matrix_sync(Cs + (warp_m * 32 + i * 16) * HCPAD + warp_n * 64 + j * 16,
                                    c[i][j], HCPAD, wmma::mem_row_major);
    __syncthreads();

    const int c4 = (tid & 31) * 4;
    const int r0 = tid >> 5;
    float4 bv = *(const float4*)(bias + n0 + c4);
    #pragma unroll
    for (int it = 0; it < 16; it++) {
        int rr = r0 + it * 8;
        size_t gi = (size_t)(m0 + rr) * GN + n0 + c4;
        float4 val = *(const float4*)(Cs + rr * HCPAD + c4);
        val.x += bv.x; val.y += bv.y; val.z += bv.z; val.w += bv.w;
        if (addend) {
            uint2 au = *(const uint2*)(addend + gi);
            __half2 a01 = u2h(au.x), a23 = u2h(au.y);
            val.x += __low2float(a01);  val.y += __high2float(a01);
            val.z += __low2float(a23);  val.w += __high2float(a23);
        }
        if (sizeof(OutT) == 2) {
            uint2 o;
            o.x = h2u(__floats2half2_rn(val.x, val.y));
            o.y = h2u(__floats2half2_rn(val.z, val.w));
            *(uint2*)((__half*)C + gi) = o;
        } else {
            *(float4*)((float*)C + gi) = val;
        }
    }
}

template <typename OutT>
__global__ __launch_bounds__(256, 2) void gemm_h(
    const __half* __restrict__ X, const __half* __restrict__ W,
    const float* __restrict__ bias, const __half* __restrict__ addend,
    OutT* __restrict__ C)
{
    extern __shared__ __half hsm[];
    gemm_core<OutT>(X, W, bias, addend, C, hsm, blockIdx.y * HBM, blockIdx.x * HBN);
}

// merged q/k/v projections: blockIdx.z selects the problem
struct QKVArgs {
    const __half* x[3];
    const __half* w[3];
    const float*  bias[3];
    const __half* add[3];
    __half*       c[3];
};

__global__ __launch_bounds__(256, 2) void gemm_qkv(QKVArgs args)
{
    extern __shared__ __half hsm[];
    const int z = blockIdx.z;
    gemm_core<__half>(args.x[z], args.w[z], args.bias[z], args.add[z], args.c[z],
                      hsm, blockIdx.y * HBM, blockIdx.x * HBN);
}

// ================= register-softmax attention (mma.m16n8k16 PTX) =================
#define AKP 72                       // halves per K/V row (conflict-free ldmatrix: 9 x 16B)
#define ATK_BUFH (64 * AKP)          // halves per tile buffer (4608)
#define EXPC 0.180336880111f         // log2(e) / 8
#define AT_SMEM_BYTES ((4 * ATK_BUFH + 128) * 2)   // K0,K1,V0,V1 + msh[2][32] half2 = 37120 B

__device__ __forceinline__ void mma16816(float* d, const uint32_t* a, uint32_t b0, uint32_t b1) {
    asm volatile(
        "mma.sync.aligned.m16n8k16.row.col.f32.f16.f16.f32 "
        "{%0,%1,%2,%3}, {%4,%5,%6,%7}, {%8,%9}, {%0,%1,%2,%3};"
        : "+f"(d[0]), "+f"(d[1]), "+f"(d[2]), "+f"(d[3])
        : "r"(a[0]), "r"(a[1]), "r"(a[2]), "r"(a[3]), "r"(b0), "r"(b1));
}
__device__ __forceinline__ void ldmx4(uint32_t& r0, uint32_t& r1, uint32_t& r2, uint32_t& r3,
                                      uint32_t addr) {
    asm volatile("ldmatrix.sync.aligned.m8n8.x4.shared.b16 {%0,%1,%2,%3}, [%4];"
                 : "=r"(r0), "=r"(r1), "=r"(r2), "=r"(r3) : "r"(addr));
}
__device__ __forceinline__ void ldmx4t(uint32_t& r0, uint32_t& r1, uint32_t& r2, uint32_t& r3,
                                       uint32_t addr) {
    asm volatile("ldmatrix.sync.aligned.m8n8.x4.trans.shared.b16 {%0,%1,%2,%3}, [%4];"
                 : "=r"(r0), "=r"(r1), "=r"(r2), "=r"(r3) : "r"(addr));
}
__device__ __forceinline__ void stg_cs32(void* p, uint32_t v) {
    asm volatile("st.global.cs.b32 [%0], %1;" :: "l"(p), "r"(v) : "memory");
}

__global__ __launch_bounds__(128, 4) void attn_kernel(
    const __half* __restrict__ gq, const __half* __restrict__ gk, const __half* __restrict__ gv,
    const int* __restrict__ mask, __half* __restrict__ ps, __half* __restrict__ go,
    float* __restrict__ rinv_out)
{
    extern __shared__ __half asm_[];
    __half2* msh = (__half2*)(asm_ + 4 * ATK_BUFH);   // [2][32]
    const uint32_t smb = smem_u32(asm_);

    const int tid  = threadIdx.x;
    const int wid  = tid >> 5;         // 4 warps, each 16 q-rows
    const int lane = tid & 31;
    const int gid  = lane >> 2;        // row-in-8
    const int tig  = lane & 3;         // thread-in-group
    const int b = blockIdx.z, h = blockIdx.y;
    const int q0 = blockIdx.x * 64;

    const __half* Kb = gk + ((size_t)(b * LL)) * DD + h * DKH;
    const __half* Vb = gv + ((size_t)(b * LL)) * DD + h * DKH;

    // ---- Q a-fragments (held in regs whole kernel): 4 k-chunks of 16 ----
    uint32_t aq[4][4];
    {
        const __half* Qw = gq + ((size_t)(b * LL + q0 + wid * 16)) * DD + h * DKH;
        #pragma unroll
        for (int kc = 0; kc < 4; kc++) {
            aq[kc][0] = *(const uint32_t*)(Qw + (size_t)gid * DD       + kc * 16 + tig * 2);
            aq[kc][1] = *(const uint32_t*)(Qw + (size_t)(gid + 8) * DD + kc * 16 + tig * 2);
            aq[kc][2] = *(const uint32_t*)(Qw + (size_t)gid * DD       + kc * 16 + 8 + tig * 2);
            aq[kc][3] = *(const uint32_t*)(Qw + (size_t)(gid + 8) * DD + kc * 16 + 8 + tig * 2);
        }
    }

    float of_[8][4];
    #pragma unroll
    for (int nc = 0; nc < 8; nc++)
        #pragma unroll
        for (int j = 0; j < 4; j++) of_[nc][j] = 0.0f;

    float rs0 = 0.0f, rs1 = 0.0f;

    const int mbase = b * LL;
    const size_t psrow0 = ((size_t)(b * HH + h) * LL + q0 + wid * 16 + gid) * LL;
    const size_t psrow1 = psrow0 + 8 * (size_t)LL;

    // stage K+V tile kt into buffer kt&1 (1024 x 16B chunks, 8/thread)
    auto stageKV = [&](int kt) {
        const int buf = kt & 1;
        const __half* Ksrc = Kb + (size_t)(kt * 64) * DD;
        const __half* Vsrc = Vb + (size_t)(kt * 64) * DD;
        const uint32_t kb = smb + (uint32_t)(buf * ATK_BUFH) * 2;
        const uint32_t vb = smb + (uint32_t)((2 + buf) * ATK_BUFH) * 2;
        #pragma unroll
        for (int j = 0; j < 4; j++) {
            int idx = tid + 128 * j;
            int rr = idx >> 3, c8 = (idx & 7) * 8;
            cpa16h(kb + (uint32_t)(rr * AKP + c8) * 2, Ksrc + (size_t)rr * DD + c8);
            cpa16h(vb + (uint32_t)(rr * AKP + c8) * 2, Vsrc + (size_t)rr * DD + c8);
        }
        asm volatile("cp.async.commit_group;\n");
    };

    stageKV(0);

    const int si = lane & 7;            // ldmatrix source-row index
    const int selk = (lane >> 3) & 1;
    const int seln = (lane >> 4) & 1;

    for (int kt = 0; kt < 32; kt++) {
        const int buf = kt & 1;
        asm volatile("cp.async.wait_group 0;\n");
        if (tid < 32) {
            int m0v = mask[mbase + kt * 64 + tid * 2];
            int m1v = mask[mbase + kt * 64 + tid * 2 + 1];
            msh[buf * 32 + tid] = __halves2half2(__int2half_rn(m0v), __int2half_rn(m1v));
        }
        __syncthreads();   // KV[buf] + msh[buf] visible; prior reads of this buf done

        if (kt + 1 < 32) stageKV(kt + 1);

        // ---- S = Q K^T (regs) ----
        const uint32_t kaddr = smb + (uint32_t)(buf * ATK_BUFH) * 2;
        float sc[8][4];
        #pragma unroll
        for (int nc = 0; nc < 8; nc++)
            #pragma unroll
            for (int j = 0; j < 4; j++) sc[nc][j] = 0.0f;

        #pragma unroll
        for (int kc = 0; kc < 4; kc++) {
            #pragma unroll
            for (int ncp = 0; ncp < 4; ncp++) {
                // K[n][k] row-major == B col-major: non-trans ldmatrix
                uint32_t ad = kaddr +
                    (uint32_t)((ncp * 16 + seln * 8 + si) * AKP + kc * 16 + selk * 8) * 2;
                uint32_t b0, b1, b2, b3;
                ldmx4(b0, b1, b2, b3, ad);
                mma16816(sc[2 * ncp],     aq[kc], b0, b1);
                mma16816(sc[2 * ncp + 1], aq[kc], b2, b3);
            }
        }

        // ---- p = mask * exp2(S*log2e/8); rowsum; stream P to gmem; keep P as a-frags ----
        uint32_t ph01[8], ph23[8];
        const __half2* mrow = msh + buf * 32;
        #pragma unroll
        for (int nc = 0; nc < 8; nc++) {
            __half2 m = mrow[nc * 4 + tig];
            uint32_t x01 = h2u(__floats2half2_rn(sc[nc][0] * EXPC, sc[nc][1] * EXPC));
            uint32_t x23 = h2u(__floats2half2_rn(sc[nc][2] * EXPC, sc[nc][3] * EXPC));
            uint32_t e01, e23;
            asm("ex2.approx.f16x2 %0, %1;" : "=r"(e01) : "r"(x01));
            asm("ex2.approx.f16x2 %0, %1;" : "=r"(e23) : "r"(x23));
            __half2 p01 = __hmul2(u2h(e01), m);
            __half2 p23 = __hmul2(u2h(e23), m);
            float2 f01 = __half22float2(p01);
            float2 f23 = __half22float2(p23);
            rs0 += f01.x + f01.y;
            rs1 += f23.x + f23.y;
            ph01[nc] = h2u(p01);
            ph23[nc] = h2u(p23);
            int col0 = nc * 8 + tig * 2;
            stg_cs32(ps + psrow0 + kt * 64 + col0, ph01[nc]);
            stg_cs32(ps + psrow1 + kt * 64 + col0, ph23[nc]);
        }

        // ---- O += P V (P from regs; c-frag layout == a-frag layout) ----
        const uint32_t vaddr = smb + (uint32_t)((2 + buf) * ATK_BUFH) * 2;
        #pragma unroll
        for (int kc = 0; kc < 4; kc++) {
            uint32_t ap[4] = { ph01[2 * kc], ph23[2 * kc], ph01[2 * kc + 1], ph23[2 * kc + 1] };
            #pragma unroll
            for (int ncp = 0; ncp < 4; ncp++) {
                // V[k][n] row-major: trans ldmatrix for B
                uint32_t ad = vaddr +
                    (uint32_t)((kc * 16 + selk * 8 + si) * AKP + ncp * 16 + seln * 8) * 2;
                uint32_t b0, b1, b2, b3;
                ldmx4t(b0, b1, b2, b3, ad);
                mma16816(of_[2 * ncp],     ap, b0, b1);
                mma16816(of_[2 * ncp + 1], ap, b2, b3);
            }
        }
    }

    // ---- rowsums (quad reduce) ----
    rs0 += __shfl_xor_sync(0xffffffff, rs0, 1);
    rs0 += __shfl_xor_sync(0xffffffff, rs0, 2);
    rs1 += __shfl_xor_sync(0xffffffff, rs1, 1);
    rs1 += __shfl_xor_sync(0xffffffff, rs1, 2);
    const float rv0 = 1.0f / rs0;
    const float rv1 = 1.0f / rs1;
    if (tig == 0) {
        size_t ribase = (size_t)(b * HH + h) * LL + q0 + wid * 16 + gid;
        rinv_out[ribase]     = rv0;
        rinv_out[ribase + 8] = rv1;
    }

    // ---- O epilogue: normalize, write half ----
    __half* go0 = go + (size_t)(b * LL + q0 + wid * 16 + gid) * DD + h * DKH;
    __half* go1 = go0 + 8 * (size_t)DD;
    #pragma unroll
    for (int nc = 0; nc < 8; nc++) {
        int col0 = nc * 8 + tig * 2;
        *(uint32_t*)(go0 + col0) = h2u(__floats2half2_rn(of_[nc][0] * rv0, of_[nc][1] * rv0));
        *(uint32_t*)(go1 + col0) = h2u(__floats2half2_rn(of_[nc][2] * rv1, of_[nc][3] * rv1));
    }
}

// ================= rescale: half P -> normalized f32 attn =================
__global__ __launch_bounds__(256) void rescale_kernel(
    const uint4* __restrict__ ps4, const float* __restrict__ rinv,
    float4* __restrict__ attn4)
{
    size_t f = (size_t)blockIdx.x * 256 + threadIdx.x;
    float s = __ldg(rinv + (f >> 8));
    uint4 u = __ldcs(ps4 + f);
    __half2 h0 = u2h(u.x), h1 = u2h(u.y);
    __half2 h2v = u2h(u.z), h3 = u2h(u.w);
    float4 o0, o1;
    o0.x = __low2float(h0) * s;  o0.y = __high2float(h0) * s;
    o0.z = __low2float(h1) * s;  o0.w = __high2float(h1) * s;
    o1.x = __low2float(h2v) * s; o1.y = __high2float(h2v) * s;
    o1.z = __low2float(h3) * s;  o1.w = __high2float(h3) * s;
    __stcs(attn4 + f * 2,     o0);
    __stcs(attn4 + f * 2 + 1, o1);
}

// ================= launch =================
extern "C" void kernel_launch(void* const* d_in, const int* in_sizes, int n_in,
                              void* d_out, int out_size)
{
    const float* q      = (const float*)d_in[0];
    const float* k      = (const float*)d_in[1];
    const float* v      = (const float*)d_in[2];
    const float* semf   = (const float*)d_in[3];
    const int*   mask   = (const int*)  d_in[4];
    const float* w_q    = (const float*)d_in[5];
    const float* b_q    = (const float*)d_in[6];
    const float* w_k    = (const float*)d_in[7];
    const float* b_k    = (const float*)d_in[8];
    const float* w_v    = (const float*)d_in[9];
    const float* b_v    = (const float*)d_in[10];
    const float* w_sem  = (const float*)d_in[11];
    const float* b_sem  = (const float*)d_in[12];
    const float* w_out  = (const float*)d_in[13];
    const float* b_out  = (const float*)d_in[14];

    float* out = (float*)d_out;
    const size_t attn_elems = (size_t)BB * HH * LL * LL;
    size_t attn_off = ((size_t)out_size >= attn_elems) ? (size_t)out_size - attn_elems : 0;
    float* attn = out + attn_off;

    __half *p_qx, *p_kx, *p_vx, *p_sx, *p_wq, *p_wk, *p_wv, *p_ws, *p_wo;
    __half *p_semo, *p_qp, *p_kp, *p_vp, *p_op, *p_ps;
    float *p_ri;
    cudaGetSymbolAddress((void**)&p_qx, g_qx);
    cudaGetSymbolAddress((void**)&p_kx, g_kx);
    cudaGetSymbolAddress((void**)&p_vx, g_vx);
    cudaGetSymbolAddress((void**)&p_sx, g_sx);
    cudaGetSymbolAddress((void**)&p_wq, g_wq);
    cudaGetSymbolAddress((void**)&p_wk, g_wk);
    cudaGetSymbolAddress((void**)&p_wv, g_wv);
    cudaGetSymbolAddress((void**)&p_ws, g_ws);
    cudaGetSymbolAddress((void**)&p_wo, g_wo);
    cudaGetSymbolAddress((void**)&p_semo, g_semo);
    cudaGetSymbolAddress((void**)&p_qp, g_qp);
    cudaGetSymbolAddress((void**)&p_kp, g_kp);
    cudaGetSymbolAddress((void**)&p_vp, g_vp);
    cudaGetSymbolAddress((void**)&p_op, g_op);
    cudaGetSymbolAddress((void**)&p_ps, g_ps);
    cudaGetSymbolAddress((void**)&p_ri, g_rinv);

    const size_t NBL = (size_t)BB * LL * DD;
    const size_t NW  = (size_t)DD * DD;

    cvt_inputs<<<dim3((unsigned)(NBL / 2048), 4), 256>>>(
        (const float4*)q, (const float4*)k, (const float4*)v, (const float4*)semf,
        (uint4*)p_qx, (uint4*)p_kx, (uint4*)p_vx, (uint4*)p_sx);
    cvt_weights<<<dim3((unsigned)(NW / 2048), 5), 256>>>(
        (const float4*)w_q, (const float4*)w_k, (const float4*)w_v,
        (const float4*)w_sem, (const float4*)w_out,
        (uint4*)p_wq, (uint4*)p_wk, (uint4*)p_wv, (uint4*)p_ws, (uint4*)p_wo);

    cudaFuncSetAttribute(gemm_h<__half>, cudaFuncAttributeMaxDynamicSharedMemorySize, HSMEM_BYTES);
    cudaFuncSetAttribute(gemm_h<float>,  cudaFuncAttributeMaxDynamicSharedMemorySize, HSMEM_BYTES);
    cudaFuncSetAttribute(gemm_qkv,       cudaFuncAttributeMaxDynamicSharedMemorySize, HSMEM_BYTES);

    dim3 gg(GN / HBN, (BB * LL) / HBM);   // (8, 64)

    // sem projection first (k/v consume it)
    gemm_h<__half><<<gg, 256, HSMEM_BYTES>>>(p_sx, p_ws, b_sem, nullptr, p_semo);

    // merged q/k/v projections
    QKVArgs qa;
    qa.x[0] = p_qx;  qa.x[1] = p_kx;  qa.x[2] = p_vx;
    qa.w[0] = p_wq;  qa.w[1] = p_wk;  qa.w[2] = p_wv;
    qa.bias[0] = b_q; qa.bias[1] = b_k; qa.bias[2] = b_v;
    qa.add[0] = nullptr; qa.add[1] = p_semo; qa.add[2] = p_semo;
    qa.c[0] = p_qp;  qa.c[1] = p_kp;  qa.c[2] = p_vp;
    gemm_qkv<<<dim3(GN / HBN, (BB * LL) / HBM, 3), 256, HSMEM_BYTES>>>(qa);

    attn_kernel<<<dim3(LL / 64, HH, BB), 128, AT_SMEM_BYTES>>>(
        p_qp, p_kp, p_vp, mask, p_ps, p_op, p_ri);

    rescale_kernel<<<(unsigned)(attn_elems / 2048), 256>>>((const uint4*)p_ps, p_ri, (float4*)attn);

    gemm_h<float><<<gg, 256, HSMEM_BYTES>>>(p_op, p_wo, b_out, nullptr, out);
}